// round 1
// baseline (speedup 1.0000x reference)
#include <cuda_runtime.h>
#include <cstdint>
#include <cmath>

#define NLEV 16

struct LevelP {
    int      sres;                 // 3D res (grid-1), same for x,y,z
    unsigned ss1, ss2;             // dense strides (grid, grid^2)
    unsigned soff;                 // entry offset into sembeddings
    int      shash;                // 1 if hashed (size 2^19)
    int      trest;                // 4D t-dim res (xyz res == sres)
    unsigned ts1, ts2, ts3;        // dense strides
    unsigned toff;
    int      thash;
};

struct AllP { LevelP lv[NLEV]; };

__global__ __launch_bounds__(256, 2)
void st_grid_encoder_kernel(const float4* __restrict__ inp,
                            const float2* __restrict__ semb,
                            const float2* __restrict__ temb,
                            const float*  __restrict__ memb,
                            float* __restrict__ out,
                            int B, AllP P)
{
    int b = blockIdx.x * blockDim.x + threadIdx.x;
    if (b >= B) return;

    float4 q = inp[b];

    // ---------------- mask: dense trilinear on 128^3 ----------------
    float mx = q.x * 127.0f, my = q.y * 127.0f, mz = q.z * 127.0f;
    float fmx = floorf(mx), fmy = floorf(my), fmz = floorf(mz);
    int   mx0 = (int)fmx,  my0 = (int)fmy,  mz0 = (int)fmz;
    float gx = mx - fmx, gy = my - fmy, gz = mz - fmz;
    float mwx[2] = {1.0f - gx, gx};
    float mwy[2] = {1.0f - gy, gy};
    float mwz[2] = {1.0f - gz, gz};

    float mv[8];
    #pragma unroll
    for (int c = 0; c < 8; c++) {
        unsigned bx = c & 1, by = (c >> 1) & 1, bz = (c >> 2) & 1;
        unsigned idx = (unsigned)(mx0 + bx) + (unsigned)(my0 + by) * 128u
                     + (unsigned)(mz0 + bz) * 16384u;
        mv[c] = __ldg(memb + idx);
    }
    float mraw = 0.0f;
    #pragma unroll
    for (int c = 0; c < 8; c++) {
        float w = mwx[c & 1] * mwy[(c >> 1) & 1] * mwz[(c >> 2) & 1];
        mraw += w * mv[c];
    }
    float m  = 1.0f / (1.0f + expf(-mraw));
    float om = 1.0f - m;

    float* op = out + (size_t)b * (2 * NLEV);

    #pragma unroll 1
    for (int l = 0; l < NLEV; l++) {
        const LevelP p = P.lv[l];

        // shared xyz lattice coords for this level (3D res == 4D xyz res)
        float sr = (float)p.sres;
        float px = q.x * sr, py = q.y * sr, pz = q.z * sr;
        float fpx = floorf(px), fpy = floorf(py), fpz = floorf(pz);
        unsigned ix = (unsigned)(int)fpx;
        unsigned iy = (unsigned)(int)fpy;
        unsigned iz = (unsigned)(int)fpz;
        float hx = px - fpx, hy = py - fpy, hz = pz - fpz;
        float ax[2] = {1.0f - hx, hx};
        float ay[2] = {1.0f - hy, hy};
        float az[2] = {1.0f - hz, hz};

        // -------- spatial 3D: 8 corners, batched loads --------
        float2 sv[8];
        #pragma unroll
        for (int c = 0; c < 8; c++) {
            unsigned bx = c & 1, by = (c >> 1) & 1, bz = (c >> 2) & 1;
            unsigned idx;
            if (p.shash) {
                idx = ((ix + bx) ^ (iy + by) * 2654435761u
                                 ^ (iz + bz) * 805459861u) & 524287u;
            } else {
                idx = (ix + bx) + (iy + by) * p.ss1 + (iz + bz) * p.ss2;
            }
            sv[c] = __ldg(semb + p.soff + idx);
        }
        float s0 = 0.0f, s1 = 0.0f;
        #pragma unroll
        for (int c = 0; c < 8; c++) {
            float w = ax[c & 1] * ay[(c >> 1) & 1] * az[(c >> 2) & 1];
            s0 += w * sv[c].x;
            s1 += w * sv[c].y;
        }

        // -------- temporal 4D: 16 corners, batched loads --------
        float pw  = q.w * (float)p.trest;
        float fpw = floorf(pw);
        unsigned iw = (unsigned)(int)fpw;
        float hw = pw - fpw;
        float aw[2] = {1.0f - hw, hw};

        float2 tv[16];
        #pragma unroll
        for (int c = 0; c < 16; c++) {
            unsigned bx = c & 1, by = (c >> 1) & 1, bz = (c >> 2) & 1, bw = (c >> 3) & 1;
            unsigned idx;
            if (p.thash) {
                idx = ((ix + bx) ^ (iy + by) * 2654435761u
                                 ^ (iz + bz) * 805459861u
                                 ^ (iw + bw) * 3674653429u) & 524287u;
            } else {
                idx = (ix + bx) + (iy + by) * p.ts1 + (iz + bz) * p.ts2
                                + (iw + bw) * p.ts3;
            }
            tv[c] = __ldg(temb + p.toff + idx);
        }
        float t0 = 0.0f, t1 = 0.0f;
        #pragma unroll
        for (int c = 0; c < 16; c++) {
            float w = ax[c & 1] * ay[(c >> 1) & 1] * az[(c >> 2) & 1] * aw[(c >> 3) & 1];
            t0 += w * tv[c].x;
            t1 += w * tv[c].y;
        }

        op[2 * l]     = m * s0 + om * t0;
        op[2 * l + 1] = m * s1 + om * t1;
    }
}

extern "C" void kernel_launch(void* const* d_in, const int* in_sizes, int n_in,
                              void* d_out, int out_size)
{
    const float4* inp  = (const float4*)d_in[0];
    const float2* semb = (const float2*)d_in[1];
    const float2* temb = (const float2*)d_in[2];
    const float*  memb = (const float*)d_in[3];
    float* out = (float*)d_out;

    int B = in_sizes[0] / 4;

    // Host-side replication of _level_grids (float64, matching numpy exactly).
    AllP P;
    long long soff = 0, toff = 0;
    for (int l = 0; l < NLEV; l++) {
        double p147 = pow(1.447, (double)l);
        double p115 = pow(1.15,  (double)l);

        long long sres  = (long long)ceil(16.0 * p147);
        long long sgrid = sres + 1;
        long long sprod = sgrid * sgrid * sgrid;
        long long sparams = sprod < 524288LL ? sprod : 524288LL;
        sparams = ((sparams + 7) / 8) * 8;

        P.lv[l].sres  = (int)sres;
        P.lv[l].ss1   = (unsigned)sgrid;
        P.lv[l].ss2   = (unsigned)(sgrid * sgrid);
        P.lv[l].soff  = (unsigned)soff;
        P.lv[l].shash = (sprod > sparams) ? 1 : 0;
        soff += sparams;

        long long trest = (long long)ceil(16.0 * p115);
        long long tgx = sres + 1;            // xyz grid identical to 3D
        long long tgt = trest + 1;
        long long tprod = tgx * tgx * tgx * tgt;
        long long tparams = tprod < 524288LL ? tprod : 524288LL;
        tparams = ((tparams + 7) / 8) * 8;

        P.lv[l].trest = (int)trest;
        P.lv[l].ts1   = (unsigned)tgx;
        P.lv[l].ts2   = (unsigned)(tgx * tgx);
        P.lv[l].ts3   = (unsigned)(tgx * tgx * tgx);   // only used when dense
        P.lv[l].toff  = (unsigned)toff;
        P.lv[l].thash = (tprod > tparams) ? 1 : 0;
        toff += tparams;
    }

    int threads = 256;
    int blocks  = (B + threads - 1) / threads;
    st_grid_encoder_kernel<<<blocks, threads>>>(inp, semb, temb, memb, out, B, P);
}

// round 3
// speedup vs baseline: 1.3137x; 1.3137x over previous
#include <cuda_runtime.h>
#include <cstdint>
#include <cmath>

#define NLEV 16
#define TPB  256
#define PITCH 33   // 32 floats + 1 pad, bank-conflict-free staging

struct LevelP {
    int      sres;                 // 3D res (grid-1), same for x,y,z
    unsigned ss1, ss2;             // dense strides (grid, grid^2)
    unsigned soff;                 // entry offset into sembeddings
    int      shash;                // 1 if hashed (size 2^19)
    int      trest;                // 4D t-dim res (xyz res == sres)
    unsigned ts1, ts2, ts3;        // dense strides
    unsigned toff;
    int      thash;
};

struct AllP { LevelP lv[NLEV]; };

// Load a corner pair. If the two indices form an aligned {2k, 2k+1} pair
// (always true for hashed x-pairs with even ix, and for dense pairs with
// even base index), use one 16B load -> 1 L1 wavefront instead of 2.
__device__ __forceinline__ void gather2(const float2* __restrict__ tab,
                                        unsigned i0, unsigned i1,
                                        float2& c0, float2& c1)
{
    if ((i0 ^ i1) == 1u) {
        const float4 v = __ldg(reinterpret_cast<const float4*>(tab + (i0 & ~1u)));
        const float2 lo = make_float2(v.x, v.y);
        const float2 hi = make_float2(v.z, v.w);
        const bool sw = (i0 & 1u);
        c0 = sw ? hi : lo;
        c1 = sw ? lo : hi;
    } else {
        c0 = __ldg(tab + i0);
        c1 = __ldg(tab + i1);
    }
}

__global__ __launch_bounds__(TPB, 2)
void st_grid_encoder_kernel(const float4* __restrict__ inp,
                            const float2* __restrict__ semb,
                            const float2* __restrict__ temb,
                            const float*  __restrict__ memb,
                            float* __restrict__ out,
                            int B, AllP P)
{
    __shared__ float sbuf[TPB * PITCH];

    const int tid = threadIdx.x;
    const int b   = blockIdx.x * TPB + tid;
    const bool active = (b < B);

    if (active) {
        float4 q = inp[b];

        // ---------------- mask: dense trilinear on 128^3 ----------------
        float mx = q.x * 127.0f, my = q.y * 127.0f, mz = q.z * 127.0f;
        float fmx = floorf(mx), fmy = floorf(my), fmz = floorf(mz);
        unsigned mx0 = (unsigned)(int)fmx, my0 = (unsigned)(int)fmy, mz0 = (unsigned)(int)fmz;
        float gx = mx - fmx, gy = my - fmy, gz = mz - fmz;
        float mwx[2] = {1.0f - gx, gx};
        float mwy[2] = {1.0f - gy, gy};
        float mwz[2] = {1.0f - gz, gz};

        float mv[8];
        #pragma unroll
        for (int p = 0; p < 4; p++) {
            unsigned by = p & 1, bz = (p >> 1) & 1;
            unsigned i0 = mx0 + (my0 + by) * 128u + (mz0 + bz) * 16384u;
            unsigned i1 = i0 + 1u;
            if ((i0 ^ i1) == 1u) {
                float2 v = __ldg(reinterpret_cast<const float2*>(memb + (i0 & ~1u)));
                mv[2 * p] = v.x; mv[2 * p + 1] = v.y;
            } else {
                mv[2 * p]     = __ldg(memb + i0);
                mv[2 * p + 1] = __ldg(memb + i1);
            }
        }
        float mraw = 0.0f;
        #pragma unroll
        for (int c = 0; c < 8; c++) {
            unsigned p = c >> 1, bx = c & 1;
            float w = mwx[bx] * mwy[p & 1] * mwz[(p >> 1) & 1];
            mraw += w * mv[c];
        }
        float m  = 1.0f / (1.0f + expf(-mraw));
        float om = 1.0f - m;

        float* sp = sbuf + tid * PITCH;

        #pragma unroll 1
        for (int l = 0; l < NLEV; l++) {
            const LevelP p = P.lv[l];

            float sr = (float)p.sres;
            float px = q.x * sr, py = q.y * sr, pz = q.z * sr;
            float fpx = floorf(px), fpy = floorf(py), fpz = floorf(pz);
            unsigned ix = (unsigned)(int)fpx;
            unsigned iy = (unsigned)(int)fpy;
            unsigned iz = (unsigned)(int)fpz;
            float hx = px - fpx, hy = py - fpy, hz = pz - fpz;
            float ax[2] = {1.0f - hx, hx};
            float ay[2] = {1.0f - hy, hy};
            float az[2] = {1.0f - hz, hz};

            // partial yz hashes shared between s and t
            unsigned ryz[4];
            #pragma unroll
            for (int pp = 0; pp < 4; pp++) {
                unsigned by = pp & 1, bz = (pp >> 1) & 1;
                ryz[pp] = (iy + by) * 2654435761u ^ (iz + bz) * 805459861u;
            }

            // -------- spatial 3D: 4 x-pairs --------
            float2 sv[8];
            #pragma unroll
            for (int pp = 0; pp < 4; pp++) {
                unsigned by = pp & 1, bz = (pp >> 1) & 1;
                unsigned i0, i1;
                if (p.shash) {
                    i0 = (ix ^ ryz[pp]) & 524287u;
                    i1 = ((ix + 1u) ^ ryz[pp]) & 524287u;
                } else {
                    i0 = ix + (iy + by) * p.ss1 + (iz + bz) * p.ss2;
                    i1 = i0 + 1u;
                }
                gather2(semb + p.soff, i0, i1, sv[2 * pp], sv[2 * pp + 1]);
            }
            float s0 = 0.0f, s1 = 0.0f;
            #pragma unroll
            for (int c = 0; c < 8; c++) {
                unsigned pp = c >> 1, bx = c & 1;
                float w = ax[bx] * ay[pp & 1] * az[(pp >> 1) & 1];
                s0 += w * sv[c].x;
                s1 += w * sv[c].y;
            }

            // -------- temporal 4D: 8 x-pairs --------
            float pw  = q.w * (float)p.trest;
            float fpw = floorf(pw);
            unsigned iw = (unsigned)(int)fpw;
            float hw = pw - fpw;
            float aw[2] = {1.0f - hw, hw};

            float2 tv[16];
            #pragma unroll
            for (int pp = 0; pp < 8; pp++) {
                unsigned by = pp & 1, bz = (pp >> 1) & 1, bw = (pp >> 2) & 1;
                unsigned i0, i1;
                if (p.thash) {
                    unsigned r = ryz[pp & 3] ^ (iw + bw) * 3674653429u;
                    i0 = (ix ^ r) & 524287u;
                    i1 = ((ix + 1u) ^ r) & 524287u;
                } else {
                    i0 = ix + (iy + by) * p.ts1 + (iz + bz) * p.ts2
                            + (iw + bw) * p.ts3;
                    i1 = i0 + 1u;
                }
                gather2(temb + p.toff, i0, i1, tv[2 * pp], tv[2 * pp + 1]);
            }
            float t0 = 0.0f, t1 = 0.0f;
            #pragma unroll
            for (int c = 0; c < 16; c++) {
                unsigned pp = c >> 1, bx = c & 1;
                float w = ax[bx] * ay[pp & 1] * az[(pp >> 1) & 1] * aw[(pp >> 2) & 1];
                t0 += w * tv[c].x;
                t1 += w * tv[c].y;
            }

            sp[2 * l]     = m * s0 + om * t0;
            sp[2 * l + 1] = m * s1 + om * t1;
        }
    }

    __syncthreads();

    // ---- coalesced flush: block's 256 points x 32 floats = 2048 float4 ----
    const int base = blockIdx.x * TPB;
    if (base + TPB <= B) {
        float4* o4 = reinterpret_cast<float4*>(out + (size_t)base * (2 * NLEV));
        #pragma unroll
        for (int i = 0; i < 8; i++) {
            int g  = i * TPB + tid;        // float4 index within block tile
            int pl = g >> 3;               // local point
            int c4 = (g & 7) * 4;          // float offset within point
            const float* s = sbuf + pl * PITCH + c4;
            float4 v;
            v.x = s[0]; v.y = s[1]; v.z = s[2]; v.w = s[3];
            o4[g] = v;
        }
    } else {
        int nrem = (B - base) * (2 * NLEV);
        for (int g = tid; g < nrem; g += TPB) {
            int pl = g >> 5, c = g & 31;
            out[(size_t)base * (2 * NLEV) + g] = sbuf[pl * PITCH + c];
        }
    }
}

extern "C" void kernel_launch(void* const* d_in, const int* in_sizes, int n_in,
                              void* d_out, int out_size)
{
    const float4* inp  = (const float4*)d_in[0];
    const float2* semb = (const float2*)d_in[1];
    const float2* temb = (const float2*)d_in[2];
    const float*  memb = (const float*)d_in[3];
    float* out = (float*)d_out;

    int B = in_sizes[0] / 4;

    AllP P;
    long long soff = 0, toff = 0;
    for (int l = 0; l < NLEV; l++) {
        double p147 = pow(1.447, (double)l);
        double p115 = pow(1.15,  (double)l);

        long long sres  = (long long)ceil(16.0 * p147);
        long long sgrid = sres + 1;
        long long sprod = sgrid * sgrid * sgrid;
        long long sparams = sprod < 524288LL ? sprod : 524288LL;
        sparams = ((sparams + 7) / 8) * 8;

        P.lv[l].sres  = (int)sres;
        P.lv[l].ss1   = (unsigned)sgrid;
        P.lv[l].ss2   = (unsigned)(sgrid * sgrid);
        P.lv[l].soff  = (unsigned)soff;
        P.lv[l].shash = (sprod > sparams) ? 1 : 0;
        soff += sparams;

        long long trest = (long long)ceil(16.0 * p115);
        long long tgx = sres + 1;
        long long tgt = trest + 1;
        long long tprod = tgx * tgx * tgx * tgt;
        long long tparams = tprod < 524288LL ? tprod : 524288LL;
        tparams = ((tparams + 7) / 8) * 8;

        P.lv[l].trest = (int)trest;
        P.lv[l].ts1   = (unsigned)tgx;
        P.lv[l].ts2   = (unsigned)(tgx * tgx);
        P.lv[l].ts3   = (unsigned)(tgx * tgx * tgx);
        P.lv[l].toff  = (unsigned)toff;
        P.lv[l].thash = (tprod > tparams) ? 1 : 0;
        toff += tparams;
    }

    int threads = TPB;
    int blocks  = (B + threads - 1) / threads;
    st_grid_encoder_kernel<<<blocks, threads>>>(inp, semb, temb, memb, out, B, P);
}